// round 2
// baseline (speedup 1.0000x reference)
#include <cuda_runtime.h>
#include <cstdint>

// Problem constants (fixed by the reference)
#define HW      65536            // 256*256
#define BATCH   8
#define C0      128
#define NPIX    (BATCH * HW)     // 524288
#define THREADS 256
#define PIX_PER_BLOCK (THREADS * 2)
#define NBLOCKS (NPIX / PIX_PER_BLOCK)   // 1024

// Shared-memory weight layout, float2 units.
// Layer i stored as [c][o/2] where element = {w[o][c], w[o+1][c]} (output-pair packed).
#define OFF1 0        // 128 x 32 -> 4096
#define OFF2 4096     // 64 x 16  -> 1024
#define OFF3 5120     // 32 x 8   -> 256
#define OFF4 5376     // 16 x 4   -> 64
#define OFF5 5440     // 8 x 2    -> 16
#define OFF6 5456     // 4 x 1    -> 4
#define OFF7 5460     // 1        -> 1   ({w7[0], w7[1]})
#define SMEM_F2 5461

__device__ __forceinline__ float2 ffma2(float2 a, float2 b, float2 c) {
    unsigned long long ra = reinterpret_cast<unsigned long long&>(a);
    unsigned long long rb = reinterpret_cast<unsigned long long&>(b);
    unsigned long long rc = reinterpret_cast<unsigned long long&>(c);
    unsigned long long rd;
    asm("fma.rn.f32x2 %0, %1, %2, %3;" : "=l"(rd) : "l"(ra), "l"(rb), "l"(rc));
    return reinterpret_cast<float2&>(rd);
}

__device__ __forceinline__ float2 leaky2(float2 v) {
    v.x = fmaxf(v.x, 0.01f * v.x);
    v.y = fmaxf(v.y, 0.01f * v.y);
    return v;
}

// Stage weight matrix w[COUT][CIN] (row-major in global) into shared as
// dst[c*(COUT/2) + o2] = {w[2*o2][c], w[2*o2+1][c]}   (transposed, output-pair packed)
__device__ __forceinline__ void stage_pairs(float2* dst, const float* __restrict__ w,
                                            int cout, int cin, int tid) {
    int npair = (cout / 2) * cin;
    for (int i = tid; i < npair; i += THREADS) {
        int o2 = i / cin;
        int c  = i - o2 * cin;
        dst[c * (cout / 2) + o2] =
            make_float2(w[(2 * o2) * cin + c], w[(2 * o2 + 1) * cin + c]);
    }
}

// Dense layer for 2 pixels with output-pair packing.
// in0/in1: channel-pair-packed activations (CIN/2 float2) for pixel 0 / pixel 1.
// acc0/acc1: COUT/2 float2 outputs (channel-pair packed).
template <int CIN, int COUT>
__device__ __forceinline__ void layer2px(const float2* __restrict__ sw,
                                         const float2* in0, const float2* in1,
                                         float2* acc0, float2* acc1) {
    constexpr int O2 = COUT / 2;
#pragma unroll
    for (int o = 0; o < O2; ++o) { acc0[o] = make_float2(0.f, 0.f); acc1[o] = make_float2(0.f, 0.f); }

#pragma unroll 2
    for (int c2 = 0; c2 < CIN / 2; ++c2) {
        float2 v0 = in0[c2];
        float2 v1 = in1[c2];
#pragma unroll
        for (int h = 0; h < 2; ++h) {
            float s0 = h ? v0.y : v0.x;
            float s1 = h ? v1.y : v1.x;
            float2 d0 = make_float2(s0, s0);
            float2 d1 = make_float2(s1, s1);
            const float2* wr = sw + (2 * c2 + h) * O2;
            if constexpr ((O2 & 1) == 0) {
                const float4* w4 = reinterpret_cast<const float4*>(wr);
#pragma unroll
                for (int o4 = 0; o4 < O2 / 2; ++o4) {
                    float4 wp = w4[o4];
                    float2 wa = make_float2(wp.x, wp.y);
                    float2 wb = make_float2(wp.z, wp.w);
                    acc0[2 * o4]     = ffma2(d0, wa, acc0[2 * o4]);
                    acc1[2 * o4]     = ffma2(d1, wa, acc1[2 * o4]);
                    acc0[2 * o4 + 1] = ffma2(d0, wb, acc0[2 * o4 + 1]);
                    acc1[2 * o4 + 1] = ffma2(d1, wb, acc1[2 * o4 + 1]);
                }
            } else {
#pragma unroll
                for (int o = 0; o < O2; ++o) {
                    float2 wp = wr[o];
                    acc0[o] = ffma2(d0, wp, acc0[o]);
                    acc1[o] = ffma2(d1, wp, acc1[o]);
                }
            }
        }
    }
}

__global__ __launch_bounds__(THREADS, 1)
void fused_mlp7_kernel(const float* __restrict__ x,
                       const float* __restrict__ w1, const float* __restrict__ w2,
                       const float* __restrict__ w3, const float* __restrict__ w4,
                       const float* __restrict__ w5, const float* __restrict__ w6,
                       const float* __restrict__ w7,
                       float* __restrict__ out) {
    __shared__ float2 sw[SMEM_F2];
    const int tid = threadIdx.x;

    stage_pairs(sw + OFF1, w1, 64, 128, tid);
    stage_pairs(sw + OFF2, w2, 32, 64, tid);
    stage_pairs(sw + OFF3, w3, 16, 32, tid);
    stage_pairs(sw + OFF4, w4, 8, 16, tid);
    stage_pairs(sw + OFF5, w5, 4, 8, tid);
    stage_pairs(sw + OFF6, w6, 2, 4, tid);
    if (tid == 0) sw[OFF7] = make_float2(w7[0], w7[1]);
    __syncthreads();

    // Two adjacent pixels per thread
    const int g = (blockIdx.x * THREADS + tid) * 2;
    const int b = g >> 16;           // image index (block never straddles images)
    const int p = g & (HW - 1);      // pixel within image

    const float* xp = x + (size_t)b * (C0 * HW) + p;

    // ---- Layer 1: 128 -> 64, x streamed from global with 4-deep prefetch ----
    float2 a0_0[32], a0_1[32];
#pragma unroll
    for (int o = 0; o < 32; ++o) { a0_0[o] = make_float2(0.f, 0.f); a0_1[o] = make_float2(0.f, 0.f); }

    float2 xbuf[4];
#pragma unroll
    for (int k = 0; k < 4; ++k)
        xbuf[k] = *reinterpret_cast<const float2*>(xp + (size_t)k * HW);

    for (int c = 0; c < 128; c += 4) {
        float2 cur[4];
#pragma unroll
        for (int k = 0; k < 4; ++k) cur[k] = xbuf[k];
#pragma unroll
        for (int k = 0; k < 4; ++k) {
            int cn = c + 4 + k;
            if (cn < 128)
                xbuf[k] = *reinterpret_cast<const float2*>(xp + (size_t)cn * HW);
        }
#pragma unroll
        for (int k = 0; k < 4; ++k) {
            float2 d0 = make_float2(cur[k].x, cur[k].x);   // pixel 0
            float2 d1 = make_float2(cur[k].y, cur[k].y);   // pixel 1
            const float4* w4 = reinterpret_cast<const float4*>(sw + OFF1 + (c + k) * 32);
#pragma unroll
            for (int o4 = 0; o4 < 16; ++o4) {
                float4 wp = w4[o4];
                float2 wa = make_float2(wp.x, wp.y);
                float2 wb = make_float2(wp.z, wp.w);
                a0_0[2 * o4]     = ffma2(d0, wa, a0_0[2 * o4]);
                a0_1[2 * o4]     = ffma2(d1, wa, a0_1[2 * o4]);
                a0_0[2 * o4 + 1] = ffma2(d0, wb, a0_0[2 * o4 + 1]);
                a0_1[2 * o4 + 1] = ffma2(d1, wb, a0_1[2 * o4 + 1]);
            }
        }
    }
#pragma unroll
    for (int o = 0; o < 32; ++o) { a0_0[o] = leaky2(a0_0[o]); a0_1[o] = leaky2(a0_1[o]); }

    // ---- Layers 2..6 with LeakyReLU ----
    float2 a1_0[16], a1_1[16];
    layer2px<64, 32>(sw + OFF2, a0_0, a0_1, a1_0, a1_1);
#pragma unroll
    for (int o = 0; o < 16; ++o) { a1_0[o] = leaky2(a1_0[o]); a1_1[o] = leaky2(a1_1[o]); }

    float2 a2_0[8], a2_1[8];
    layer2px<32, 16>(sw + OFF3, a1_0, a1_1, a2_0, a2_1);
#pragma unroll
    for (int o = 0; o < 8; ++o) { a2_0[o] = leaky2(a2_0[o]); a2_1[o] = leaky2(a2_1[o]); }

    float2 a3_0[4], a3_1[4];
    layer2px<16, 8>(sw + OFF4, a2_0, a2_1, a3_0, a3_1);
#pragma unroll
    for (int o = 0; o < 4; ++o) { a3_0[o] = leaky2(a3_0[o]); a3_1[o] = leaky2(a3_1[o]); }

    float2 a4_0[2], a4_1[2];
    layer2px<8, 4>(sw + OFF5, a3_0, a3_1, a4_0, a4_1);
#pragma unroll
    for (int o = 0; o < 2; ++o) { a4_0[o] = leaky2(a4_0[o]); a4_1[o] = leaky2(a4_1[o]); }

    float2 a5_0[1], a5_1[1];
    layer2px<4, 2>(sw + OFF6, a4_0, a4_1, a5_0, a5_1);
    a5_0[0] = leaky2(a5_0[0]);
    a5_1[0] = leaky2(a5_1[0]);

    // ---- Layer 7: 2 -> 1, no activation ----
    float2 w7p = sw[OFF7];
    float r0 = fmaf(a5_0[0].x, w7p.x, a5_0[0].y * w7p.y);
    float r1 = fmaf(a5_1[0].x, w7p.x, a5_1[0].y * w7p.y);

    *reinterpret_cast<float2*>(out + g) = make_float2(r0, r1);
}

extern "C" void kernel_launch(void* const* d_in, const int* in_sizes, int n_in,
                              void* d_out, int out_size) {
    const float* x  = (const float*)d_in[0];
    const float* w1 = (const float*)d_in[1];
    const float* w2 = (const float*)d_in[2];
    const float* w3 = (const float*)d_in[3];
    const float* w4 = (const float*)d_in[4];
    const float* w5 = (const float*)d_in[5];
    const float* w6 = (const float*)d_in[6];
    const float* w7 = (const float*)d_in[7];
    float* out = (float*)d_out;

    fused_mlp7_kernel<<<NBLOCKS, THREADS>>>(x, w1, w2, w3, w4, w5, w6, w7, out);
}

// round 3
// speedup vs baseline: 8.9329x; 8.9329x over previous
#include <cuda_runtime.h>
#include <cstdint>

// Problem constants (fixed by the reference)
#define HW      65536            // 256*256
#define BATCH   8
#define C0      128
#define NPIX    (BATCH * HW)     // 524288
#define THREADS 256
#define PIX_PER_BLOCK (THREADS * 2)
#define NBLOCKS (NPIX / PIX_PER_BLOCK)   // 1024

// Shared-memory weight layout, float2 units.
// Layer i stored as [c][o/2] where element = {w[o][c], w[o+1][c]} (output-pair packed).
#define OFF1 0        // 128 x 32 -> 4096
#define OFF2 4096     // 64 x 16  -> 1024
#define OFF3 5120     // 32 x 8   -> 256
#define OFF4 5376     // 16 x 4   -> 64
#define OFF5 5440     // 8 x 2    -> 16
#define OFF6 5456     // 4 x 1    -> 4
#define OFF7 5460     // 1        -> 1   ({w7[0], w7[1]})
#define SMEM_F2 5461

__device__ __forceinline__ float2 ffma2(float2 a, float2 b, float2 c) {
    unsigned long long ra = reinterpret_cast<unsigned long long&>(a);
    unsigned long long rb = reinterpret_cast<unsigned long long&>(b);
    unsigned long long rc = reinterpret_cast<unsigned long long&>(c);
    unsigned long long rd;
    asm("fma.rn.f32x2 %0, %1, %2, %3;" : "=l"(rd) : "l"(ra), "l"(rb), "l"(rc));
    return reinterpret_cast<float2&>(rd);
}

__device__ __forceinline__ float2 leaky2(float2 v) {
    v.x = fmaxf(v.x, 0.01f * v.x);
    v.y = fmaxf(v.y, 0.01f * v.y);
    return v;
}

// Stage weight matrix w[COUT][CIN] (row-major in global) into shared as
// dst[c*(COUT/2) + o2] = {w[2*o2][c], w[2*o2+1][c]}   (transposed, output-pair packed)
__device__ __forceinline__ void stage_pairs(float2* dst, const float* __restrict__ w,
                                            int cout, int cin, int tid) {
    int npair = (cout / 2) * cin;
    for (int i = tid; i < npair; i += THREADS) {
        int o2 = i / cin;
        int c  = i - o2 * cin;
        dst[c * (cout / 2) + o2] =
            make_float2(w[(2 * o2) * cin + c], w[(2 * o2 + 1) * cin + c]);
    }
}

// Dense layer for 2 pixels with output-pair packing. FULLY UNROLLED so all
// register-array indices are compile-time constants (no local-mem demotion).
// in0/in1: channel-pair-packed activations (CIN/2 float2) for pixel 0 / pixel 1.
// acc0/acc1: COUT/2 float2 outputs (channel-pair packed).
template <int CIN, int COUT>
__device__ __forceinline__ void layer2px(const float2* __restrict__ sw,
                                         const float2* in0, const float2* in1,
                                         float2* acc0, float2* acc1) {
    constexpr int O2 = COUT / 2;
#pragma unroll
    for (int o = 0; o < O2; ++o) { acc0[o] = make_float2(0.f, 0.f); acc1[o] = make_float2(0.f, 0.f); }

#pragma unroll
    for (int c2 = 0; c2 < CIN / 2; ++c2) {
        float2 v0 = in0[c2];
        float2 v1 = in1[c2];
#pragma unroll
        for (int h = 0; h < 2; ++h) {
            float s0 = h ? v0.y : v0.x;
            float s1 = h ? v1.y : v1.x;
            float2 d0 = make_float2(s0, s0);
            float2 d1 = make_float2(s1, s1);
            const float2* wr = sw + (2 * c2 + h) * O2;
            if constexpr ((O2 & 1) == 0) {
                const float4* w4 = reinterpret_cast<const float4*>(wr);
#pragma unroll
                for (int o4 = 0; o4 < O2 / 2; ++o4) {
                    float4 wp = w4[o4];
                    float2 wa = make_float2(wp.x, wp.y);
                    float2 wb = make_float2(wp.z, wp.w);
                    acc0[2 * o4]     = ffma2(d0, wa, acc0[2 * o4]);
                    acc1[2 * o4]     = ffma2(d1, wa, acc1[2 * o4]);
                    acc0[2 * o4 + 1] = ffma2(d0, wb, acc0[2 * o4 + 1]);
                    acc1[2 * o4 + 1] = ffma2(d1, wb, acc1[2 * o4 + 1]);
                }
            } else {
#pragma unroll
                for (int o = 0; o < O2; ++o) {
                    float2 wp = wr[o];
                    acc0[o] = ffma2(d0, wp, acc0[o]);
                    acc1[o] = ffma2(d1, wp, acc1[o]);
                }
            }
        }
    }
}

__global__ __launch_bounds__(THREADS, 1)
void fused_mlp7_kernel(const float* __restrict__ x,
                       const float* __restrict__ w1, const float* __restrict__ w2,
                       const float* __restrict__ w3, const float* __restrict__ w4,
                       const float* __restrict__ w5, const float* __restrict__ w6,
                       const float* __restrict__ w7,
                       float* __restrict__ out) {
    __shared__ float2 sw[SMEM_F2];
    const int tid = threadIdx.x;

    stage_pairs(sw + OFF1, w1, 64, 128, tid);
    stage_pairs(sw + OFF2, w2, 32, 64, tid);
    stage_pairs(sw + OFF3, w3, 16, 32, tid);
    stage_pairs(sw + OFF4, w4, 8, 16, tid);
    stage_pairs(sw + OFF5, w5, 4, 8, tid);
    stage_pairs(sw + OFF6, w6, 2, 4, tid);
    if (tid == 0) sw[OFF7] = make_float2(w7[0], w7[1]);
    __syncthreads();

    // Two adjacent pixels per thread
    const int g = (blockIdx.x * THREADS + tid) * 2;
    const int b = g >> 16;           // image index (block never straddles images)
    const int p = g & (HW - 1);      // pixel within image

    const float* xp = x + (size_t)b * (C0 * HW) + p;

    // ---- Layer 1: 128 -> 64, x streamed from global with 4-deep prefetch ----
    float2 a0_0[32], a0_1[32];
#pragma unroll
    for (int o = 0; o < 32; ++o) { a0_0[o] = make_float2(0.f, 0.f); a0_1[o] = make_float2(0.f, 0.f); }

    float2 xbuf[4];
#pragma unroll
    for (int k = 0; k < 4; ++k)
        xbuf[k] = *reinterpret_cast<const float2*>(xp + (size_t)k * HW);

    for (int c = 0; c < 128; c += 4) {
        float2 cur[4];
#pragma unroll
        for (int k = 0; k < 4; ++k) cur[k] = xbuf[k];
        if (c + 4 < 128) {
#pragma unroll
            for (int k = 0; k < 4; ++k)
                xbuf[k] = *reinterpret_cast<const float2*>(xp + (size_t)(c + 4 + k) * HW);
        }
#pragma unroll
        for (int k = 0; k < 4; ++k) {
            float2 d0 = make_float2(cur[k].x, cur[k].x);   // pixel 0
            float2 d1 = make_float2(cur[k].y, cur[k].y);   // pixel 1
            const float4* w4 = reinterpret_cast<const float4*>(sw + OFF1 + (c + k) * 32);
#pragma unroll
            for (int o4 = 0; o4 < 16; ++o4) {
                float4 wp = w4[o4];
                float2 wa = make_float2(wp.x, wp.y);
                float2 wb = make_float2(wp.z, wp.w);
                a0_0[2 * o4]     = ffma2(d0, wa, a0_0[2 * o4]);
                a0_1[2 * o4]     = ffma2(d1, wa, a0_1[2 * o4]);
                a0_0[2 * o4 + 1] = ffma2(d0, wb, a0_0[2 * o4 + 1]);
                a0_1[2 * o4 + 1] = ffma2(d1, wb, a0_1[2 * o4 + 1]);
            }
        }
    }
#pragma unroll
    for (int o = 0; o < 32; ++o) { a0_0[o] = leaky2(a0_0[o]); a0_1[o] = leaky2(a0_1[o]); }

    // ---- Layers 2..6 with LeakyReLU ----
    float2 a1_0[16], a1_1[16];
    layer2px<64, 32>(sw + OFF2, a0_0, a0_1, a1_0, a1_1);
#pragma unroll
    for (int o = 0; o < 16; ++o) { a1_0[o] = leaky2(a1_0[o]); a1_1[o] = leaky2(a1_1[o]); }

    float2 a2_0[8], a2_1[8];
    layer2px<32, 16>(sw + OFF3, a1_0, a1_1, a2_0, a2_1);
#pragma unroll
    for (int o = 0; o < 8; ++o) { a2_0[o] = leaky2(a2_0[o]); a2_1[o] = leaky2(a2_1[o]); }

    float2 a3_0[4], a3_1[4];
    layer2px<16, 8>(sw + OFF4, a2_0, a2_1, a3_0, a3_1);
#pragma unroll
    for (int o = 0; o < 4; ++o) { a3_0[o] = leaky2(a3_0[o]); a3_1[o] = leaky2(a3_1[o]); }

    float2 a4_0[2], a4_1[2];
    layer2px<8, 4>(sw + OFF5, a3_0, a3_1, a4_0, a4_1);
#pragma unroll
    for (int o = 0; o < 2; ++o) { a4_0[o] = leaky2(a4_0[o]); a4_1[o] = leaky2(a4_1[o]); }

    float2 a5_0[1], a5_1[1];
    layer2px<4, 2>(sw + OFF6, a4_0, a4_1, a5_0, a5_1);
    a5_0[0] = leaky2(a5_0[0]);
    a5_1[0] = leaky2(a5_1[0]);

    // ---- Layer 7: 2 -> 1, no activation ----
    float2 w7p = sw[OFF7];
    float r0 = fmaf(a5_0[0].x, w7p.x, a5_0[0].y * w7p.y);
    float r1 = fmaf(a5_1[0].x, w7p.x, a5_1[0].y * w7p.y);

    *reinterpret_cast<float2*>(out + g) = make_float2(r0, r1);
}

extern "C" void kernel_launch(void* const* d_in, const int* in_sizes, int n_in,
                              void* d_out, int out_size) {
    const float* x  = (const float*)d_in[0];
    const float* w1 = (const float*)d_in[1];
    const float* w2 = (const float*)d_in[2];
    const float* w3 = (const float*)d_in[3];
    const float* w4 = (const float*)d_in[4];
    const float* w5 = (const float*)d_in[5];
    const float* w6 = (const float*)d_in[6];
    const float* w7 = (const float*)d_in[7];
    float* out = (float*)d_out;

    fused_mlp7_kernel<<<NBLOCKS, THREADS>>>(x, w1, w2, w3, w4, w5, w6, w7, out);
}